// round 15
// baseline (speedup 1.0000x reference)
#include <cuda_runtime.h>
#include <cuda_fp16.h>
#include <math.h>
#include <stdint.h>

// Problem constants
#define NB  32
#define C   150
#define H   56
#define W   56
#define HW  3136
#define O   225
#define D   1350
#define SPLIT 75

// Padded image: [NB][58][58][160] fp16, channels-last, zero borders/pad chans
#define PH 58
#define PW 58
#define PC 160

// GEMM geometry (K reordered tap-major: d' = tap*160 + c)
#define KP2 1440                  // 9 taps * 160 padded channels = 45*32
#define KCH 45
#define ROWS_IMG  3200            // HW padded to 25*128 (measured faster than exact M)
#define MROWS     (NB * ROWS_IMG) // 102400
#define BM 128
#define BN 128
#define BK 32
#define NST 2
#define ASTR 40                   // smem row stride in halfs (80B)
#define A_BYTES (BM * ASTR * 2)   // 10240
#define B_BYTES (BN * ASTR * 2)   // 10240
#define STAGE   (A_BYTES + B_BYTES)
// dynamic smem: max(pipeline 2*20480=40960, split epilogue 64*132*4=33792)
#define SMEM_GEMM 40960

// Scratch (__device__ globals; no cudaMalloc allowed)
__device__ float g_p2[O];
__device__ float g_s [NB * HW];
__device__ float g_x2[NB * HW];
__device__ __align__(256) unsigned short x_pad[(size_t)NB * PH * PW * PC];
__device__ __align__(256) unsigned short B_pad[256 * KP2];

// ---------------------------------------------------------------------------
static __device__ __forceinline__ uint32_t s2u(const void* p) {
    uint32_t a;
    asm("{ .reg .u64 t; cvta.to.shared.u64 t, %1; cvt.u32.u64 %0, t; }"
        : "=r"(a) : "l"(p));
    return a;
}

static __device__ __forceinline__ void cpasync16(uint32_t dst, const void* src) {
    asm volatile("cp.async.cg.shared.global [%0], [%1], 16;"
                 :: "r"(dst), "l"(src));
}
static __device__ __forceinline__ void cpasync16z(uint32_t dst, const void* src,
                                                  uint32_t srcsz) {
    asm volatile("cp.async.cg.shared.global [%0], [%1], 16, %2;"
                 :: "r"(dst), "l"(src), "r"(srcsz));
}

static __device__ __forceinline__ void ldsm4(uint32_t* r, uint32_t addr) {
    asm volatile("ldmatrix.sync.aligned.m8n8.x4.shared.b16 {%0,%1,%2,%3}, [%4];"
                 : "=r"(r[0]), "=r"(r[1]), "=r"(r[2]), "=r"(r[3])
                 : "r"(addr));
}

// fp16 inputs, fp16 accumulate
static __device__ __forceinline__ void mma16816h(uint32_t* d, const uint32_t* a,
                                                 uint32_t b0, uint32_t b1) {
    asm volatile(
        "mma.sync.aligned.m16n8k16.row.col.f16.f16.f16.f16 "
        "{%0,%1}, {%2,%3,%4,%5}, {%6,%7}, {%0,%1};"
        : "+r"(d[0]), "+r"(d[1])
        : "r"(a[0]), "r"(a[1]), "r"(a[2]), "r"(a[3]), "r"(b0), "r"(b1));
}

static __device__ __forceinline__ unsigned short f2h(float v) {
    __half h = __float2half(v);
    __half_raw r = (__half_raw)h;
    return r.x;
}

// ---------------------------------------------------------------------------
// Fused weight prep: one block per padded o (256 blocks).
//  B_pad[o, tap*160+c] = fp16( weight[o, c*9+tap] * wc(c) )
//  g_p2[o]             = sum_d wc * weight^2      (block reduction)
// ---------------------------------------------------------------------------
__global__ void bprep_kernel(const float* __restrict__ wt) {
    int o = blockIdx.x;
    int t = threadIdx.x;
    float s = 0.f;
    for (int pp = t; pp < KP2 / 2; pp += 256) {
        int tap = pp / (PC / 2);
        int cp  = pp - tap * (PC / 2);
        int c0  = cp * 2;
        unsigned short r[2];
        #pragma unroll
        for (int e = 0; e < 2; e++) {
            int c = c0 + e;
            float v = 0.f;
            if (o < O && c < C) {
                float wv = wt[o * D + c * 9 + tap];
                float wc = (c < SPLIT) ? 0.25f : 0.75f;
                v = wv * wc;
                s += wc * wv * wv;
            }
            r[e] = f2h(v);
        }
        *reinterpret_cast<unsigned int*>(&B_pad[o * KP2 + tap * PC + c0]) =
            *reinterpret_cast<unsigned int*>(r);
    }
    // reduce p2
    #pragma unroll
    for (int off = 16; off > 0; off >>= 1)
        s += __shfl_down_sync(0xffffffffu, s, off);
    __shared__ float red[8];
    if ((t & 31) == 0) red[t >> 5] = s;
    __syncthreads();
    if (t == 0 && o < O) {
        float tot = 0.f;
        #pragma unroll
        for (int i = 0; i < 8; i++) tot += red[i];
        g_p2[o] = tot;
    }
}

// ---------------------------------------------------------------------------
// box: x2[n,h,w] = 3x3 zero-padded box sum of g_s
// ---------------------------------------------------------------------------
__global__ void box_kernel() {
    int i = blockIdx.x * 256 + threadIdx.x;
    if (i >= NB * HW) return;
    int n = i / HW, hw = i % HW;
    int h = hw / W, w = hw % W;
    float s = 0.f;
    #pragma unroll
    for (int dh = -1; dh <= 1; dh++) {
        int hh = h + dh;
        if (hh < 0 || hh >= H) continue;
        #pragma unroll
        for (int dw = -1; dw <= 1; dw++) {
            int ww = w + dw;
            if (ww < 0 || ww >= W) continue;
            s += g_s[n * HW + hh * W + ww];
        }
    }
    g_x2[i] = s;
}

// ---------------------------------------------------------------------------
// Fused x prep (single pass over x):
//  x_pad[n][gh][gw][c] = fp16(x[n,c,gh-1,gw-1]) interior, 0 on borders/pad c.
//  g_s[n, gh-1, w]     = sum_c wc * x^2
// ---------------------------------------------------------------------------
__global__ void xpad_kernel(const float* __restrict__ x) {
    __shared__ float sm[C * W];   // 8400 floats
    int n  = blockIdx.x / PH;
    int gh = blockIdx.x % PH;
    int t  = threadIdx.x;
    bool rowv = (gh >= 1 && gh <= H);
    if (rowv) {
        const float* src = x + ((size_t)n * C * H + (size_t)(gh - 1)) * W;
        for (int idx = t; idx < C * W; idx += 256) {
            int c = idx / W, w = idx - c * W;
            sm[idx] = src[(size_t)c * H * W + w];
        }
    }
    __syncthreads();
    unsigned short* dst = x_pad + ((size_t)n * PH + gh) * PW * PC;
    for (int idx = t; idx < PW * (PC / 2); idx += 256) {
        int gw = idx / (PC / 2);
        int cp = idx - gw * (PC / 2);
        int c  = cp * 2;
        unsigned short r[2] = {0, 0};
        if (rowv && gw >= 1 && gw <= W) {
            if (c < C)     r[0] = f2h(sm[c * W + gw - 1]);
            if (c + 1 < C) r[1] = f2h(sm[(c + 1) * W + gw - 1]);
        }
        *reinterpret_cast<unsigned int*>(&dst[gw * PC + c]) =
            *reinterpret_cast<unsigned int*>(r);
    }
    // fused chansum: threads 0..W-1 each reduce one pixel column of this row
    if (rowv && t < W) {
        float s = 0.f;
        #pragma unroll 5
        for (int c = 0; c < C; c++) {
            float v = sm[c * W + t];
            float wc = (c < SPLIT) ? 0.25f : 0.75f;
            s += wc * v * v;
        }
        g_s[n * HW + (gh - 1) * W + t] = s;
    }
}

// ---------------------------------------------------------------------------
// Fused im2col GEMM via mma.sync fp16 + distance epilogue.
// CTA: 128 M x 128 N, 256 threads (8 warps, 4M x 2N, warp tile 32x64),
// K = 45 chunks of 32 tap-major, double-buffered cp.async,
// one barrier per chunk, split 2-pass epilogue.
// Occupancy target: 4 CTAs/SM (32 warps) — 64-reg cap, 40KB smem.
// ---------------------------------------------------------------------------
__global__ __launch_bounds__(256, 4)
void gemm_kernel(float* __restrict__ out) {
    extern __shared__ __align__(128) unsigned char smem[];
    const uint32_t sbase = s2u(smem);
    const int t    = threadIdx.x;
    const int warp = t >> 5, lane = t & 31;
    const int m_base = blockIdx.x * BM;
    const int n_base = blockIdx.y * BN;
    const int img = m_base / ROWS_IMG;
    const int hw0 = m_base % ROWS_IMG;
    const int warp_m = (warp & 3) * 32;
    const int warp_n = (warp >> 2) * 64;

    // ---- loader coords: row = t>>1 (0..127), 32B half = t&1 ----
    const int r = t >> 1, hb = t & 1;
    const int hwr = hw0 + r;
    const uint32_t a_size = (hwr < HW) ? 16u : 0u;
    const int hok = (hwr < HW) ? hwr : 0;
    const int hh = hok / W, ww = hok - (hok / W) * W;
    const unsigned short* abase =
        x_pad + (((size_t)img * PH + hh) * PW + ww) * PC + hb * 16;
    const uint32_t a_dst = r * (ASTR * 2) + hb * 32;
    const unsigned short* bb0 = B_pad + (size_t)(n_base + r) * KP2 + hb * 16;
    const uint32_t b_dst = A_BYTES + r * (ASTR * 2) + hb * 32;

    uint32_t acc[2][8][2];
    #pragma unroll
    for (int a = 0; a < 2; a++)
        #pragma unroll
        for (int b = 0; b < 8; b++) { acc[a][b][0] = 0u; acc[a][b][1] = 0u; }

    const uint32_t a_row_off = (uint32_t)(lane & 15) * (ASTR * 2);
    const uint32_t a_k_off   = (uint32_t)((lane >> 4) * 8) * 2;
    const uint32_t b_row_off = (uint32_t)((lane & 7) + ((lane >> 4) << 3)) * (ASTR * 2);
    const uint32_t b_k_off   = (uint32_t)(((lane >> 3) & 1) << 3) * 2;

    // chunk i: tap = i/5 (5 chunks of 32 == PC), A slice offset in halfs
    #define LOAD_CHUNK(i_, s_) do {                                          \
        int tap_ = (i_) / 5;                                                 \
        int kh_ = tap_ / 3, kw_ = tap_ - 3 * kh_;                            \
        int aoff_ = (kh_ * PW + kw_) * PC + ((i_) - tap_ * 5) * 32;          \
        uint32_t sb_ = sbase + (uint32_t)(s_) * STAGE;                       \
        cpasync16z(sb_ + a_dst,      abase + aoff_,     a_size);             \
        cpasync16z(sb_ + a_dst + 16, abase + aoff_ + 8, a_size);             \
        int koff_ = (i_) * 32;                                               \
        cpasync16(sb_ + b_dst,      bb0 + koff_);                            \
        cpasync16(sb_ + b_dst + 16, bb0 + koff_ + 8);                        \
    } while (0)

    // prologue: chunk 0 -> stage 0
    LOAD_CHUNK(0, 0);
    asm volatile("cp.async.commit_group;");

    #pragma unroll 1
    for (int i = 0; i < KCH; i++) {
        asm volatile("cp.async.wait_group 0;");   // chunk i resident
        __syncthreads();                          // visible to all; prev compute done

        if (i + 1 < KCH)
            LOAD_CHUNK(i + 1, (i + 1) & 1);       // overlaps compute of chunk i
        asm volatile("cp.async.commit_group;");

        const uint32_t ab = sbase + (uint32_t)(i & 1) * STAGE;
        const uint32_t bb = ab + A_BYTES;

        #pragma unroll
        for (int ks = 0; ks < 2; ks++) {
            uint32_t afr[2][4];
            #pragma unroll
            for (int mi = 0; mi < 2; mi++)
                ldsm4(afr[mi], ab + (uint32_t)(warp_m + mi * 16) * (ASTR * 2)
                              + a_row_off + (uint32_t)(ks * 32) + a_k_off);
            #pragma unroll
            for (int nj = 0; nj < 4; nj++) {
                uint32_t bfr[4];
                ldsm4(bfr, bb + (uint32_t)(warp_n + nj * 16) * (ASTR * 2)
                          + b_row_off + (uint32_t)(ks * 32) + b_k_off);
                #pragma unroll
                for (int mi = 0; mi < 2; mi++) {
                    mma16816h(acc[mi][nj * 2],     afr[mi], bfr[0], bfr[1]);
                    mma16816h(acc[mi][nj * 2 + 1], afr[mi], bfr[2], bfr[3]);
                }
            }
        }
    }
    #undef LOAD_CHUNK

    asm volatile("cp.async.wait_group 0;");
    __syncthreads();

    // -------- epilogue: two 64-o passes through smem, coalesced stores ------
    float* cs = reinterpret_cast<float*>(smem);   // [64 o][132 m]
    #pragma unroll 1
    for (int p = 0; p < 2; p++) {
        if ((warp >> 2) == p) {   // warps whose warp_n == p*64
            #pragma unroll
            for (int mi = 0; mi < 2; mi++) {
                #pragma unroll
                for (int nj = 0; nj < 8; nj++) {
                    int row = warp_m + mi * 16 + (lane >> 2);
                    int col = nj * 8 + 2 * (lane & 3);   // 0..63
                    float2 f01 = __half22float2(
                        *reinterpret_cast<const __half2*>(&acc[mi][nj][0]));
                    float2 f23 = __half22float2(
                        *reinterpret_cast<const __half2*>(&acc[mi][nj][1]));
                    cs[col * 132 + row]           = f01.x;
                    cs[(col + 1) * 132 + row]     = f01.y;
                    cs[col * 132 + row + 8]       = f23.x;
                    cs[(col + 1) * 132 + row + 8] = f23.y;
                }
            }
        }
        __syncthreads();
        #pragma unroll 4
        for (int it = 0; it < 32; it++) {
            int idx = it * 256 + t;
            int o_l = idx >> 7, m_l = idx & 127;
            int o = n_base + p * 64 + o_l, hw = hw0 + m_l;
            if (o < O && hw < HW) {
                float d2 = g_x2[img * HW + hw] + g_p2[o] - 2.f * cs[o_l * 132 + m_l];
                out[((size_t)img * O + o) * HW + hw] = sqrtf(fmaxf(d2, 1e-12f));
            }
        }
        __syncthreads();
    }
}

// ---------------------------------------------------------------------------
extern "C" void kernel_launch(void* const* d_in, const int* in_sizes, int n_in,
                              void* d_out, int out_size) {
    const float* x  = (const float*)d_in[0];   // (32,150,56,56)
    const float* wt = (const float*)d_in[1];   // (225,1350)
    float* out = (float*)d_out;                // (32,225,56,56)

    // One-time side-stream for prep overlap (host objects only)
    static cudaStream_t s_side = nullptr;
    static cudaEvent_t  s_fork = nullptr, s_join = nullptr;
    if (s_side == nullptr) {
        cudaStreamCreateWithFlags(&s_side, cudaStreamNonBlocking);
        cudaEventCreateWithFlags(&s_fork, cudaEventDisableTiming);
        cudaEventCreateWithFlags(&s_join, cudaEventDisableTiming);
    }

    cudaFuncSetAttribute(gemm_kernel,
                         cudaFuncAttributeMaxDynamicSharedMemorySize, SMEM_GEMM);

    // fork: weight prep on side stream, x prep on main stream
    cudaEventRecord(s_fork, 0);
    cudaStreamWaitEvent(s_side, s_fork, 0);
    bprep_kernel<<<256, 256, 0, s_side>>>(wt);   // B_pad + g_p2

    xpad_kernel<<<NB * PH, 256>>>(x);            // x_pad + g_s
    box_kernel<<<(NB * HW + 255) / 256, 256>>>();// g_x2

    // join
    cudaEventRecord(s_join, s_side);
    cudaStreamWaitEvent(0, s_join, 0);

    dim3 grid(MROWS / BM, 2);
    gemm_kernel<<<grid, 256, SMEM_GEMM>>>(out);
}

// round 16
// speedup vs baseline: 1.2049x; 1.2049x over previous
#include <cuda_runtime.h>
#include <cuda_fp16.h>
#include <math.h>
#include <stdint.h>

// Problem constants
#define NB  32
#define C   150
#define H   56
#define W   56
#define HW  3136
#define O   225
#define D   1350
#define SPLIT 75

// Padded image: [NB][58][58][160] fp16, channels-last, zero borders/pad chans
#define PH 58
#define PW 58
#define PC 160

// GEMM geometry (K reordered tap-major: d' = tap*160 + c)
#define KP2 1440                  // 9 taps * 160 padded channels = 45*32
#define KCH 45
#define ROWS_IMG  3200            // HW padded to 25*128 (measured faster than exact M)
#define MROWS     (NB * ROWS_IMG) // 102400
#define BM 128
#define BN 128
#define BK 32
#define NST 3
#define ASTR 40                   // smem row stride in halfs (80B)
#define A_BYTES (BM * ASTR * 2)   // 10240
#define B_BYTES (BN * ASTR * 2)   // 10240
#define STAGE   (A_BYTES + B_BYTES)
// dynamic smem: max(pipeline 3*20480=61440, epilogue 128*132*4=67584)
#define SMEM_GEMM 67584

// Scratch (__device__ globals; no cudaMalloc allowed)
__device__ float g_p2[O];
__device__ float g_s [NB * HW];
__device__ float g_x2[NB * HW];
__device__ __align__(256) unsigned short x_pad[(size_t)NB * PH * PW * PC];
__device__ __align__(256) unsigned short B_pad[256 * KP2];

// ---------------------------------------------------------------------------
static __device__ __forceinline__ uint32_t s2u(const void* p) {
    uint32_t a;
    asm("{ .reg .u64 t; cvta.to.shared.u64 t, %1; cvt.u32.u64 %0, t; }"
        : "=r"(a) : "l"(p));
    return a;
}

static __device__ __forceinline__ void cpasync16(uint32_t dst, const void* src) {
    asm volatile("cp.async.cg.shared.global [%0], [%1], 16;"
                 :: "r"(dst), "l"(src));
}
static __device__ __forceinline__ void cpasync16z(uint32_t dst, const void* src,
                                                  uint32_t srcsz) {
    asm volatile("cp.async.cg.shared.global [%0], [%1], 16, %2;"
                 :: "r"(dst), "l"(src), "r"(srcsz));
}

static __device__ __forceinline__ void ldsm4(uint32_t* r, uint32_t addr) {
    asm volatile("ldmatrix.sync.aligned.m8n8.x4.shared.b16 {%0,%1,%2,%3}, [%4];"
                 : "=r"(r[0]), "=r"(r[1]), "=r"(r[2]), "=r"(r[3])
                 : "r"(addr));
}

// fp16 inputs, fp16 accumulate
static __device__ __forceinline__ void mma16816h(uint32_t* d, const uint32_t* a,
                                                 uint32_t b0, uint32_t b1) {
    asm volatile(
        "mma.sync.aligned.m16n8k16.row.col.f16.f16.f16.f16 "
        "{%0,%1}, {%2,%3,%4,%5}, {%6,%7}, {%0,%1};"
        : "+r"(d[0]), "+r"(d[1])
        : "r"(a[0]), "r"(a[1]), "r"(a[2]), "r"(a[3]), "r"(b0), "r"(b1));
}

static __device__ __forceinline__ unsigned short f2h(float v) {
    __half h = __float2half(v);
    __half_raw r = (__half_raw)h;
    return r.x;
}

// ---------------------------------------------------------------------------
// Fused weight prep: one block per padded o (256 blocks).
//  B_pad[o, tap*160+c] = fp16( weight[o, c*9+tap] * wc(c) )
//  g_p2[o]             = sum_d wc * weight^2      (block reduction)
// ---------------------------------------------------------------------------
__global__ void bprep_kernel(const float* __restrict__ wt) {
    int o = blockIdx.x;
    int t = threadIdx.x;
    float s = 0.f;
    for (int pp = t; pp < KP2 / 2; pp += 256) {
        int tap = pp / (PC / 2);
        int cp  = pp - tap * (PC / 2);
        int c0  = cp * 2;
        unsigned short r[2];
        #pragma unroll
        for (int e = 0; e < 2; e++) {
            int c = c0 + e;
            float v = 0.f;
            if (o < O && c < C) {
                float wv = wt[o * D + c * 9 + tap];
                float wc = (c < SPLIT) ? 0.25f : 0.75f;
                v = wv * wc;
                s += wc * wv * wv;
            }
            r[e] = f2h(v);
        }
        *reinterpret_cast<unsigned int*>(&B_pad[o * KP2 + tap * PC + c0]) =
            *reinterpret_cast<unsigned int*>(r);
    }
    // reduce p2
    #pragma unroll
    for (int off = 16; off > 0; off >>= 1)
        s += __shfl_down_sync(0xffffffffu, s, off);
    __shared__ float red[8];
    if ((t & 31) == 0) red[t >> 5] = s;
    __syncthreads();
    if (t == 0 && o < O) {
        float tot = 0.f;
        #pragma unroll
        for (int i = 0; i < 8; i++) tot += red[i];
        g_p2[o] = tot;
    }
}

// ---------------------------------------------------------------------------
// box: x2[n,h,w] = 3x3 zero-padded box sum of g_s
// ---------------------------------------------------------------------------
__global__ void box_kernel() {
    int i = blockIdx.x * 256 + threadIdx.x;
    if (i >= NB * HW) return;
    int n = i / HW, hw = i % HW;
    int h = hw / W, w = hw % W;
    float s = 0.f;
    #pragma unroll
    for (int dh = -1; dh <= 1; dh++) {
        int hh = h + dh;
        if (hh < 0 || hh >= H) continue;
        #pragma unroll
        for (int dw = -1; dw <= 1; dw++) {
            int ww = w + dw;
            if (ww < 0 || ww >= W) continue;
            s += g_s[n * HW + hh * W + ww];
        }
    }
    g_x2[i] = s;
}

// ---------------------------------------------------------------------------
// Fused x prep (single pass over x):
//  x_pad[n][gh][gw][c] = fp16(x[n,c,gh-1,gw-1]) interior, 0 on borders/pad c.
//  g_s[n, gh-1, w]     = sum_c wc * x^2
// ---------------------------------------------------------------------------
__global__ void xpad_kernel(const float* __restrict__ x) {
    __shared__ float sm[C * W];   // 8400 floats
    int n  = blockIdx.x / PH;
    int gh = blockIdx.x % PH;
    int t  = threadIdx.x;
    bool rowv = (gh >= 1 && gh <= H);
    if (rowv) {
        const float* src = x + ((size_t)n * C * H + (size_t)(gh - 1)) * W;
        for (int idx = t; idx < C * W; idx += 256) {
            int c = idx / W, w = idx - c * W;
            sm[idx] = src[(size_t)c * H * W + w];
        }
    }
    __syncthreads();
    unsigned short* dst = x_pad + ((size_t)n * PH + gh) * PW * PC;
    for (int idx = t; idx < PW * (PC / 2); idx += 256) {
        int gw = idx / (PC / 2);
        int cp = idx - gw * (PC / 2);
        int c  = cp * 2;
        unsigned short r[2] = {0, 0};
        if (rowv && gw >= 1 && gw <= W) {
            if (c < C)     r[0] = f2h(sm[c * W + gw - 1]);
            if (c + 1 < C) r[1] = f2h(sm[(c + 1) * W + gw - 1]);
        }
        *reinterpret_cast<unsigned int*>(&dst[gw * PC + c]) =
            *reinterpret_cast<unsigned int*>(r);
    }
    // fused chansum: threads 0..W-1 each reduce one pixel column of this row
    if (rowv && t < W) {
        float s = 0.f;
        #pragma unroll 5
        for (int c = 0; c < C; c++) {
            float v = sm[c * W + t];
            float wc = (c < SPLIT) ? 0.25f : 0.75f;
            s += wc * v * v;
        }
        g_s[n * HW + (gh - 1) * W + t] = s;
    }
}

// ---------------------------------------------------------------------------
// Fused im2col GEMM via mma.sync fp16 + distance epilogue.
// CTA: 128 M x 128 N, 256 threads (8 warps, 4M x 2N, warp tile 32x64),
// K = 45 chunks of 32 tap-major, 3-stage cp.async (depth-2 prefetch),
// one barrier per chunk, 3 CTAs/SM. Fragment software pipeline:
// all A fragments up front, B fragments double-buffered one ahead.
// ---------------------------------------------------------------------------
__global__ __launch_bounds__(256, 3)
void gemm_kernel(float* __restrict__ out) {
    extern __shared__ __align__(128) unsigned char smem[];
    const uint32_t sbase = s2u(smem);
    const int t    = threadIdx.x;
    const int warp = t >> 5, lane = t & 31;
    const int m_base = blockIdx.x * BM;
    const int n_base = blockIdx.y * BN;
    const int img = m_base / ROWS_IMG;
    const int hw0 = m_base % ROWS_IMG;
    const int warp_m = (warp & 3) * 32;
    const int warp_n = (warp >> 2) * 64;

    // ---- loader coords: row = t>>1 (0..127), 32B half = t&1 ----
    const int r = t >> 1, hb = t & 1;
    const int hwr = hw0 + r;
    const uint32_t a_size = (hwr < HW) ? 16u : 0u;
    const int hok = (hwr < HW) ? hwr : 0;
    const int hh = hok / W, ww = hok - (hok / W) * W;
    const unsigned short* abase =
        x_pad + (((size_t)img * PH + hh) * PW + ww) * PC + hb * 16;
    const uint32_t a_dst = r * (ASTR * 2) + hb * 32;
    const unsigned short* bb0 = B_pad + (size_t)(n_base + r) * KP2 + hb * 16;
    const uint32_t b_dst = A_BYTES + r * (ASTR * 2) + hb * 32;

    uint32_t acc[2][8][2];
    #pragma unroll
    for (int a = 0; a < 2; a++)
        #pragma unroll
        for (int b = 0; b < 8; b++) { acc[a][b][0] = 0u; acc[a][b][1] = 0u; }

    const uint32_t a_row_off = (uint32_t)(lane & 15) * (ASTR * 2);
    const uint32_t a_k_off   = (uint32_t)((lane >> 4) * 8) * 2;
    const uint32_t b_row_off = (uint32_t)((lane & 7) + ((lane >> 4) << 3)) * (ASTR * 2);
    const uint32_t b_k_off   = (uint32_t)(((lane >> 3) & 1) << 3) * 2;

    // chunk i: tap = i/5 (5 chunks of 32 == PC), A slice offset in halfs
    #define LOAD_CHUNK(i_, s_) do {                                          \
        int tap_ = (i_) / 5;                                                 \
        int kh_ = tap_ / 3, kw_ = tap_ - 3 * kh_;                            \
        int aoff_ = (kh_ * PW + kw_) * PC + ((i_) - tap_ * 5) * 32;          \
        uint32_t sb_ = sbase + (uint32_t)(s_) * STAGE;                       \
        cpasync16z(sb_ + a_dst,      abase + aoff_,     a_size);             \
        cpasync16z(sb_ + a_dst + 16, abase + aoff_ + 8, a_size);             \
        int koff_ = (i_) * 32;                                               \
        cpasync16(sb_ + b_dst,      bb0 + koff_);                            \
        cpasync16(sb_ + b_dst + 16, bb0 + koff_ + 8);                        \
    } while (0)

    // prologue: chunks 0,1 -> stages 0,1
    LOAD_CHUNK(0, 0);
    asm volatile("cp.async.commit_group;");
    LOAD_CHUNK(1, 1);
    asm volatile("cp.async.commit_group;");

    int s_ld = 2, s_cp = 0;
    #pragma unroll 1
    for (int i = 0; i < KCH; i++) {
        asm volatile("cp.async.wait_group 1;");
        __syncthreads();

        if (i + 2 < KCH)
            LOAD_CHUNK(i + 2, s_ld);
        asm volatile("cp.async.commit_group;");

        const uint32_t ab = sbase + (uint32_t)s_cp * STAGE;
        const uint32_t bb = ab + A_BYTES;

        // ---- fragment software pipeline ----
        uint32_t afr[2][2][4];           // [ks][mi]
        #pragma unroll
        for (int ks = 0; ks < 2; ks++)
            #pragma unroll
            for (int mi = 0; mi < 2; mi++)
                ldsm4(afr[ks][mi], ab + (uint32_t)(warp_m + mi * 16) * (ASTR * 2)
                              + a_row_off + (uint32_t)(ks * 32) + a_k_off);

        uint32_t bfr[2][4];
        ldsm4(bfr[0], bb + (uint32_t)warp_n * (ASTR * 2) + b_row_off + b_k_off);
        int cur = 0;
        #pragma unroll
        for (int ks = 0; ks < 2; ks++) {
            #pragma unroll
            for (int nj = 0; nj < 4; nj++) {
                int nk = ks * 4 + nj + 1;
                if (nk < 8) {
                    int nks = nk >> 2, nnj = nk & 3;
                    ldsm4(bfr[cur ^ 1],
                          bb + (uint32_t)(warp_n + nnj * 16) * (ASTR * 2)
                             + b_row_off + (uint32_t)(nks * 32) + b_k_off);
                }
                #pragma unroll
                for (int mi = 0; mi < 2; mi++) {
                    mma16816h(acc[mi][nj * 2],     afr[ks][mi], bfr[cur][0], bfr[cur][1]);
                    mma16816h(acc[mi][nj * 2 + 1], afr[ks][mi], bfr[cur][2], bfr[cur][3]);
                }
                cur ^= 1;
            }
        }
        if (++s_ld == NST) s_ld = 0;
        if (++s_cp == NST) s_cp = 0;
    }
    #undef LOAD_CHUNK

    asm volatile("cp.async.wait_group 0;");
    __syncthreads();

    // -------- epilogue: transpose through smem, fused distance, coalesced ----
    float* cs = reinterpret_cast<float*>(smem);   // [128 o][132 m]
    #pragma unroll
    for (int mi = 0; mi < 2; mi++) {
        #pragma unroll
        for (int nj = 0; nj < 8; nj++) {
            int row = warp_m + mi * 16 + (lane >> 2);
            int col = warp_n + nj * 8 + 2 * (lane & 3);
            float2 f01 = __half22float2(
                *reinterpret_cast<const __half2*>(&acc[mi][nj][0]));
            float2 f23 = __half22float2(
                *reinterpret_cast<const __half2*>(&acc[mi][nj][1]));
            cs[col * 132 + row]           = f01.x;
            cs[(col + 1) * 132 + row]     = f01.y;
            cs[col * 132 + row + 8]       = f23.x;
            cs[(col + 1) * 132 + row + 8] = f23.y;
        }
    }
    __syncthreads();

    #pragma unroll 4
    for (int it = 0; it < 64; it++) {
        int idx = it * 256 + t;
        int o_l = idx >> 7, m_l = idx & 127;
        int o = n_base + o_l, hw = hw0 + m_l;
        if (o < O && hw < HW) {
            float d2 = g_x2[img * HW + hw] + g_p2[o] - 2.f * cs[o_l * 132 + m_l];
            out[((size_t)img * O + o) * HW + hw] = sqrtf(fmaxf(d2, 1e-12f));
        }
    }
}

// ---------------------------------------------------------------------------
extern "C" void kernel_launch(void* const* d_in, const int* in_sizes, int n_in,
                              void* d_out, int out_size) {
    const float* x  = (const float*)d_in[0];   // (32,150,56,56)
    const float* wt = (const float*)d_in[1];   // (225,1350)
    float* out = (float*)d_out;                // (32,225,56,56)

    // One-time side-stream for prep overlap (host objects only)
    static cudaStream_t s_side = nullptr;
    static cudaEvent_t  s_fork = nullptr, s_join = nullptr;
    if (s_side == nullptr) {
        cudaStreamCreateWithFlags(&s_side, cudaStreamNonBlocking);
        cudaEventCreateWithFlags(&s_fork, cudaEventDisableTiming);
        cudaEventCreateWithFlags(&s_join, cudaEventDisableTiming);
    }

    cudaFuncSetAttribute(gemm_kernel,
                         cudaFuncAttributeMaxDynamicSharedMemorySize, SMEM_GEMM);

    // fork: weight prep on side stream, x prep on main stream
    cudaEventRecord(s_fork, 0);
    cudaStreamWaitEvent(s_side, s_fork, 0);
    bprep_kernel<<<256, 256, 0, s_side>>>(wt);   // B_pad + g_p2

    xpad_kernel<<<NB * PH, 256>>>(x);            // x_pad + g_s
    box_kernel<<<(NB * HW + 255) / 256, 256>>>();// g_x2

    // join
    cudaEventRecord(s_join, s_side);
    cudaStreamWaitEvent(0, s_join, 0);

    dim3 grid(MROWS / BM, 2);
    gemm_kernel<<<grid, 256, SMEM_GEMM>>>(out);
}